// round 14
// baseline (speedup 1.0000x reference)
#include <cuda_runtime.h>
#include <cuda_fp16.h>
#include <math.h>
#include <stdint.h>

#define N_NODES 8192
#define N_EDGES 4096
#define HID     256
#define OUTD    128
#define NHEADS  4
#define EPS_AGG 1e-8f
#define EPS_MM  1e-8f

// -------------------- scratch (no allocations allowed) --------------------
__device__ __half   g_inc_h[(size_t)N_NODES * N_EDGES];   // fp16 incidence (64MB)
__device__ __half   g_te_h[(size_t)N_EDGES * 1024];       // fp16 te_all [4096,1024]
__device__ float    g_agg[(size_t)N_NODES * 1024];
__device__ float    g_deg[N_NODES];
__device__ __half   g_Wc_h[128 * 1024];
__device__ float    g_bc[1024];
__device__ __half   g_nf_h[(size_t)N_NODES * 128];
__device__ __half   g_ef_h[(size_t)N_EDGES * 128];
__device__ __half   g_Wn_h[4 * 128 * 256];
__device__ __half   g_Wo_h[4 * 256 * 128];
__device__ __half   g_upd_h[(size_t)N_NODES * HID];
__device__ float    g_ob[(size_t)N_NODES * OUTD];
__device__ __half   g_x_h[(size_t)N_NODES * OUTD];
__device__ unsigned g_mn[NHEADS * OUTD];
__device__ unsigned g_mx[NHEADS * OUTD];

// -------------------- helpers --------------------
__device__ __forceinline__ unsigned enc_f(float f) {
    unsigned u = __float_as_uint(f);
    return (u & 0x80000000u) ? ~u : (u | 0x80000000u);
}
__device__ __forceinline__ float dec_f(unsigned u) {
    return (u & 0x80000000u) ? __uint_as_float(u ^ 0x80000000u)
                             : __uint_as_float(~u);
}
__device__ __forceinline__ void cp16(void* dst, const void* src) {
    unsigned d = (unsigned)__cvta_generic_to_shared(dst);
    asm volatile("cp.async.cg.shared.global [%0], [%1], 16;\n" :: "r"(d), "l"(src));
}
__device__ __forceinline__ void ldsm_x4(unsigned& d0, unsigned& d1, unsigned& d2, unsigned& d3,
                                        const void* p) {
    unsigned a = (unsigned)__cvta_generic_to_shared(p);
    asm volatile("ldmatrix.sync.aligned.m8n8.x4.shared.b16 {%0,%1,%2,%3}, [%4];\n"
                 : "=r"(d0), "=r"(d1), "=r"(d2), "=r"(d3) : "r"(a));
}
__device__ __forceinline__ void ldsm_x4_t(unsigned& d0, unsigned& d1, unsigned& d2, unsigned& d3,
                                          const void* p) {
    unsigned a = (unsigned)__cvta_generic_to_shared(p);
    asm volatile("ldmatrix.sync.aligned.m8n8.x4.trans.shared.b16 {%0,%1,%2,%3}, [%4];\n"
                 : "=r"(d0), "=r"(d1), "=r"(d2), "=r"(d3) : "r"(a));
}
__device__ __forceinline__ void mma_f16(float c[4], const unsigned a[4],
                                        unsigned b0, unsigned b1) {
    asm volatile(
        "mma.sync.aligned.m16n8k16.row.col.f32.f16.f16.f32 "
        "{%0,%1,%2,%3}, {%4,%5,%6,%7}, {%8,%9}, {%0,%1,%2,%3};\n"
        : "+f"(c[0]), "+f"(c[1]), "+f"(c[2]), "+f"(c[3])
        : "r"(a[0]), "r"(a[1]), "r"(a[2]), "r"(a[3]), "r"(b0), "r"(b1));
}

// -------------------- fused f32->f16 converts (one launch) --------------------
__global__ void conv_all_kernel(const float* __restrict__ nf, const float* __restrict__ ef,
                                const float* __restrict__ Wn, const float* __restrict__ Wo,
                                __half* __restrict__ nfh, __half* __restrict__ efh,
                                __half* __restrict__ Wnh, __half* __restrict__ Woh) {
    int i = blockIdx.x * 256 + threadIdx.x;
    const float* src; __half* dst; int off;
    if (i < 262144)        { src = nf; dst = nfh; off = i; }
    else if (i < 393216)   { src = ef; dst = efh; off = i - 262144; }
    else if (i < 425984)   { src = Wn; dst = Wnh; off = i - 393216; }
    else                   { src = Wo; dst = Woh; off = i - 425984; }
    float4 v = reinterpret_cast<const float4*>(src)[off];
    __half2* o = reinterpret_cast<__half2*>(dst) + 2 * off;
    o[0] = __floats2half2_rn(v.x, v.y);
    o[1] = __floats2half2_rn(v.z, v.w);
}

// -------------------- pack We/be + init minmax --------------------
__global__ void pack_kernel(const float* __restrict__ We, const float* __restrict__ be,
                            __half* __restrict__ Wc, float* __restrict__ bc,
                            unsigned* __restrict__ mn, unsigned* __restrict__ mx) {
    int idx = blockIdx.x * blockDim.x + threadIdx.x;
    if (idx < 128 * 1024) {
        int k = idx / 1024;
        int n = idx % 1024;
        int h = n / 256, j = n % 256;
        Wc[idx] = __float2half_rn(We[((size_t)h * 128 + k) * 256 + j]);
    }
    if (idx < 1024) {
        int h = idx / 256, j = idx % 256;
        bc[idx] = be[h * 256 + j];
    }
    if (idx < NHEADS * OUTD) {
        mn[idx] = 0xFFFFFFFFu;
        mx[idx] = 0u;
    }
}

// -------------------- row degree + fp16 copy of incidence --------------------
__global__ void deg_fuse_kernel(const float* __restrict__ inc, float* __restrict__ deg,
                                __half* __restrict__ inc_h) {
    int row = blockIdx.x;
    const float4* p = reinterpret_cast<const float4*>(inc + (size_t)row * N_EDGES);
    __half2* q = reinterpret_cast<__half2*>(inc_h + (size_t)row * N_EDGES);
    float s = 0.f;
    for (int i = threadIdx.x; i < N_EDGES / 4; i += blockDim.x) {
        float4 v = p[i];
        s += (v.x + v.y) + (v.z + v.w);
        q[2 * i]     = __floats2half2_rn(v.x, v.y);
        q[2 * i + 1] = __floats2half2_rn(v.z, v.w);
    }
    #pragma unroll
    for (int o = 16; o; o >>= 1) s += __shfl_xor_sync(0xFFFFFFFFu, s, o);
    __shared__ float ws[8];
    int w = threadIdx.x >> 5, l = threadIdx.x & 31;
    if (l == 0) ws[w] = s;
    __syncthreads();
    if (threadIdx.x == 0) {
        float t = 0.f;
        #pragma unroll
        for (int i = 0; i < 8; i++) t += ws[i];
        deg[row] = t + EPS_AGG;
    }
}

// ==================== mma.sync fp16 GEMM (te + agg + out) ====================
#define BKh      32
#define A_STRIDE 40
#define B_STRIDE 136
#define A_STAGE  (128 * A_STRIDE)
#define B_STAGE  (32 * B_STRIDE)
#define NSTAGE   3
#define HGEMM_SMEM ((NSTAGE * (A_STAGE + B_STAGE)) * 2)

template <bool OUT_HALF, bool MINMAX>
__global__ __launch_bounds__(256, 2)
void hgemm_kernel(const __half* __restrict__ A, const __half* __restrict__ B,
                  void* __restrict__ Cv, int M, int N, int K,
                  const float* __restrict__ bias, const float* __restrict__ degv,
                  unsigned* __restrict__ gmn, unsigned* __restrict__ gmx) {
    extern __shared__ __half sh[];
    __half* As = sh;
    __half* Bs = sh + NSTAGE * A_STAGE;
    __shared__ unsigned cmn[128], cmx[128];

    const int tid  = threadIdx.x;
    const int lane = tid & 31;
    const int warp = tid >> 5;
    const int wm = (warp >> 2) * 64;
    const int wn = (warp & 3) * 32;
    const int g  = lane >> 2;
    const int tg = lane & 3;
    const int l16  = lane & 15;
    const int lhi8 = (lane >> 4) * 8;

    const int by = blockIdx.y * 128;
    const int bx = blockIdx.x * 128;

    if (MINMAX && tid < 128) { cmn[tid] = 0xFFFFFFFFu; cmx[tid] = 0u; }

    float acc[4][4][4];
    #pragma unroll
    for (int i = 0; i < 4; i++)
        #pragma unroll
        for (int j = 0; j < 4; j++)
            #pragma unroll
            for (int r = 0; r < 4; r++) acc[i][j][r] = 0.f;

    #define LOAD_STAGE(s, k0)                                                    \
        do {                                                                     \
            _Pragma("unroll")                                                    \
            for (int i = 0; i < 2; i++) {                                        \
                int c = tid + i * 256;                                           \
                int row = c >> 2, col = (c & 3) * 8;                             \
                cp16(As + (s) * A_STAGE + row * A_STRIDE + col,                  \
                     A + (size_t)(by + row) * K + (k0) + col);                   \
            }                                                                    \
            _Pragma("unroll")                                                    \
            for (int i = 0; i < 2; i++) {                                        \
                int c = tid + i * 256;                                           \
                int row = c >> 4, col = (c & 15) * 8;                            \
                cp16(Bs + (s) * B_STAGE + row * B_STRIDE + col,                  \
                     B + (size_t)((k0) + row) * N + bx + col);                   \
            }                                                                    \
        } while (0)

    const int nIt = K / BKh;

    LOAD_STAGE(0, 0);
    asm volatile("cp.async.commit_group;\n" ::: "memory");
    LOAD_STAGE(1, BKh);
    asm volatile("cp.async.commit_group;\n" ::: "memory");

    for (int it = 0; it < nIt; it++) {
        asm volatile("cp.async.wait_group 1;\n" ::: "memory");
        __syncthreads();
        if (it + 2 < nIt) {
            int s2 = (it + 2) % NSTAGE;
            LOAD_STAGE(s2, (it + 2) * BKh);
        }
        asm volatile("cp.async.commit_group;\n" ::: "memory");

        const int s = it % NSTAGE;
        const __half* Ab = As + s * A_STAGE;
        const __half* Bb = Bs + s * B_STAGE;

        #pragma unroll
        for (int kb = 0; kb < BKh; kb += 16) {
            unsigned af[4][4];
            #pragma unroll
            for (int mt = 0; mt < 4; mt++) {
                const __half* p = Ab + (wm + mt * 16 + l16) * A_STRIDE + kb + lhi8;
                ldsm_x4(af[mt][0], af[mt][1], af[mt][2], af[mt][3], p);
            }
            unsigned bf[2][4];
            #pragma unroll
            for (int pr = 0; pr < 2; pr++) {
                const __half* p = Bb + (kb + l16) * B_STRIDE + wn + pr * 16 + lhi8;
                ldsm_x4_t(bf[pr][0], bf[pr][1], bf[pr][2], bf[pr][3], p);
            }
            #pragma unroll
            for (int mt = 0; mt < 4; mt++)
                #pragma unroll
                for (int nt = 0; nt < 4; nt++)
                    mma_f16(acc[mt][nt], af[mt],
                            bf[nt >> 1][(nt & 1) * 2], bf[nt >> 1][(nt & 1) * 2 + 1]);
        }
        __syncthreads();
    }

    #pragma unroll
    for (int mt = 0; mt < 4; mt++) {
        int r0 = by + wm + mt * 16 + g;
        float d0 = degv ? (1.0f / degv[r0])     : 1.0f;
        float d1 = degv ? (1.0f / degv[r0 + 8]) : 1.0f;
        #pragma unroll
        for (int nt = 0; nt < 4; nt++) {
            int col = bx + wn + nt * 8 + tg * 2;
            float b0 = 0.f, b1 = 0.f;
            if (bias) { b0 = bias[col]; b1 = bias[col + 1]; }
            float v00 = (acc[mt][nt][0] + b0) * d0;
            float v01 = (acc[mt][nt][1] + b1) * d0;
            float v10 = (acc[mt][nt][2] + b0) * d1;
            float v11 = (acc[mt][nt][3] + b1) * d1;
            if (OUT_HALF) {
                __half* C = (__half*)Cv;
                *reinterpret_cast<__half2*>(C + (size_t)r0 * N + col) =
                    __floats2half2_rn(v00, v01);
                *reinterpret_cast<__half2*>(C + (size_t)(r0 + 8) * N + col) =
                    __floats2half2_rn(v10, v11);
            } else {
                float* C = (float*)Cv;
                *reinterpret_cast<float2*>(C + (size_t)r0 * N + col)       = make_float2(v00, v01);
                *reinterpret_cast<float2*>(C + (size_t)(r0 + 8) * N + col) = make_float2(v10, v11);
            }
            // store back (biased) for minmax pass below
            acc[mt][nt][0] = v00; acc[mt][nt][1] = v01;
            acc[mt][nt][2] = v10; acc[mt][nt][3] = v11;
        }
    }

    if (MINMAX) {
        __syncthreads();
        // per-thread pre-reduce over mt (same columns), then smem atomics
        #pragma unroll
        for (int nt = 0; nt < 4; nt++) {
            #pragma unroll
            for (int p = 0; p < 2; p++) {
                int col = wn + nt * 8 + tg * 2 + p;   // bx==0 for N=128
                unsigned lmn = 0xFFFFFFFFu, lmx = 0u;
                #pragma unroll
                for (int mt = 0; mt < 4; mt++) {
                    unsigned e0 = enc_f(acc[mt][nt][p]);
                    unsigned e1 = enc_f(acc[mt][nt][p + 2]);
                    lmn = min(lmn, min(e0, e1));
                    lmx = max(lmx, max(e0, e1));
                }
                atomicMin(&cmn[col], lmn);
                atomicMax(&cmx[col], lmx);
            }
        }
        __syncthreads();
        if (tid < 128) {
            atomicMin(&gmn[tid], cmn[tid]);
            atomicMax(&gmx[tid], cmx[tid]);
        }
    }
    #undef LOAD_STAGE
}

// ==================== fused tn GEMM + score + sigmoid + update ====================
// CTA tile 64x256 (full HID), K=128, 8 warps (2M x 4N), warp tile 32x64.
// upd[r,:] = sigmoid(leaky(sum_c (tn+agg)(r,c)*Wa[c] + ba)) * agg[r,:] + tn[r,:]
#define FT_APITCH 136
#define FT_BPITCH 264
#define FT_SMEM   ((64 * FT_APITCH + 128 * FT_BPITCH) * 2)

__global__ __launch_bounds__(256, 1)
void tn_score_kernel(const __half* __restrict__ X, const __half* __restrict__ Wn,
                     const float* __restrict__ bn, const float* __restrict__ Wa,
                     const float* __restrict__ ba, const float* __restrict__ aggh,
                     __half* __restrict__ upd) {
    extern __shared__ __half sh[];
    __half* As = sh;                       // [64][136]
    __half* Bs = sh + 64 * FT_APITCH;      // [128][264]
    __shared__ float s_wa[256], s_bn[256];
    __shared__ float s_row[64][4];
    __shared__ float s_co[64];

    const int tid  = threadIdx.x;
    const int lane = tid & 31;
    const int warp = tid >> 5;
    const int wm = (warp >> 2) * 32;
    const int wn = (warp & 3) * 64;
    const int g  = lane >> 2;
    const int tg = lane & 3;
    const int l16  = lane & 15;
    const int lhi8 = (lane >> 4) * 8;
    const int by = blockIdx.x * 64;

    // A: 64 rows x 128 halves (4 cp16/thread)
    #pragma unroll
    for (int i = 0; i < 4; i++) {
        int c = tid + i * 256;
        int row = c >> 4, cw = c & 15;
        cp16(As + row * FT_APITCH + cw * 8, X + (size_t)(by + row) * 128 + cw * 8);
    }
    // B: 128 rows x 256 halves (16 cp16/thread)
    #pragma unroll
    for (int i = 0; i < 16; i++) {
        int c = tid + i * 256;
        int row = c >> 5, cw = c & 31;
        cp16(Bs + row * FT_BPITCH + cw * 8, Wn + (size_t)row * 256 + cw * 8);
    }
    asm volatile("cp.async.commit_group;\n" ::: "memory");
    if (tid < 256) { s_wa[tid] = Wa[tid]; s_bn[tid] = bn[tid]; }
    asm volatile("cp.async.wait_group 0;\n" ::: "memory");
    __syncthreads();

    float acc[2][8][4];
    #pragma unroll
    for (int i = 0; i < 2; i++)
        #pragma unroll
        for (int j = 0; j < 8; j++)
            #pragma unroll
            for (int r = 0; r < 4; r++) acc[i][j][r] = 0.f;

    #pragma unroll
    for (int kb = 0; kb < 128; kb += 16) {
        unsigned af[2][4];
        #pragma unroll
        for (int mt = 0; mt < 2; mt++) {
            const __half* p = As + (wm + mt * 16 + l16) * FT_APITCH + kb + lhi8;
            ldsm_x4(af[mt][0], af[mt][1], af[mt][2], af[mt][3], p);
        }
        unsigned bf[4][4];
        #pragma unroll
        for (int pr = 0; pr < 4; pr++) {
            const __half* p = Bs + (kb + l16) * FT_BPITCH + wn + pr * 16 + lhi8;
            ldsm_x4_t(bf[pr][0], bf[pr][1], bf[pr][2], bf[pr][3], p);
        }
        #pragma unroll
        for (int mt = 0; mt < 2; mt++)
            #pragma unroll
            for (int nt = 0; nt < 8; nt++)
                mma_f16(acc[mt][nt], af[mt],
                        bf[nt >> 1][(nt & 1) * 2], bf[nt >> 1][(nt & 1) * 2 + 1]);
    }

    // ---- epilogue: bias, load agg, score partials ----
    float av[2][8][4];
    float sp[2][2] = {{0.f, 0.f}, {0.f, 0.f}};
    #pragma unroll
    for (int mt = 0; mt < 2; mt++) {
        int gr0 = by + wm + mt * 16 + g;
        #pragma unroll
        for (int nt = 0; nt < 8; nt++) {
            int col = wn + nt * 8 + tg * 2;
            float2 a0 = *reinterpret_cast<const float2*>(aggh + (size_t)gr0 * 1024 + col);
            float2 a1 = *reinterpret_cast<const float2*>(aggh + (size_t)(gr0 + 8) * 1024 + col);
            av[mt][nt][0] = a0.x; av[mt][nt][1] = a0.y;
            av[mt][nt][2] = a1.x; av[mt][nt][3] = a1.y;
            float t0 = acc[mt][nt][0] + s_bn[col];
            float t1 = acc[mt][nt][1] + s_bn[col + 1];
            float t2 = acc[mt][nt][2] + s_bn[col];
            float t3 = acc[mt][nt][3] + s_bn[col + 1];
            acc[mt][nt][0] = t0; acc[mt][nt][1] = t1;
            acc[mt][nt][2] = t2; acc[mt][nt][3] = t3;
            sp[mt][0] += (t0 + a0.x) * s_wa[col] + (t1 + a0.y) * s_wa[col + 1];
            sp[mt][1] += (t2 + a1.x) * s_wa[col] + (t3 + a1.y) * s_wa[col + 1];
        }
    }
    // reduce over tg (lanes g*4..g*4+3)
    #pragma unroll
    for (int mt = 0; mt < 2; mt++)
        #pragma unroll
        for (int hf = 0; hf < 2; hf++) {
            sp[mt][hf] += __shfl_xor_sync(0xFFFFFFFFu, sp[mt][hf], 1);
            sp[mt][hf] += __shfl_xor_sync(0xFFFFFFFFu, sp[mt][hf], 2);
        }
    if (tg == 0) {
        #pragma unroll
        for (int mt = 0; mt < 2; mt++) {
            s_row[wm + mt * 16 + g][warp & 3]     = sp[mt][0];
            s_row[wm + mt * 16 + g + 8][warp & 3] = sp[mt][1];
        }
    }
    __syncthreads();
    if (tid < 64) {
        float s = s_row[tid][0] + s_row[tid][1] + s_row[tid][2] + s_row[tid][3] + ba[0];
        s = (s > 0.f) ? s : 0.2f * s;
        s_co[tid] = 1.0f / (1.0f + expf(-s));
    }
    __syncthreads();

    #pragma unroll
    for (int mt = 0; mt < 2; mt++) {
        int lr = wm + mt * 16 + g;
        float c0 = s_co[lr];
        float c1 = s_co[lr + 8];
        int gr0 = by + lr;
        #pragma unroll
        for (int nt = 0; nt < 8; nt++) {
            int col = wn + nt * 8 + tg * 2;
            *reinterpret_cast<__half2*>(upd + (size_t)gr0 * 256 + col) =
                __floats2half2_rn(c0 * av[mt][nt][0] + acc[mt][nt][0],
                                  c0 * av[mt][nt][1] + acc[mt][nt][1]);
            *reinterpret_cast<__half2*>(upd + (size_t)(gr0 + 8) * 256 + col) =
                __floats2half2_rn(c1 * av[mt][nt][2] + acc[mt][nt][2],
                                  c1 * av[mt][nt][3] + acc[mt][nt][3]);
        }
    }
}

// -------------------- normalize + relu (dual output) --------------------
__global__ void norm_relu_kernel(const float* __restrict__ ob,
                                 const unsigned* __restrict__ mnU,
                                 const unsigned* __restrict__ mxU,
                                 __half* __restrict__ xh, float* __restrict__ xf) {
    int idx = blockIdx.x * blockDim.x + threadIdx.x;
    int c = idx & 127;
    float mn = dec_f(mnU[c]);
    float mx = dec_f(mxU[c]);
    float v = (ob[idx] - mn) / (mx - mn + EPS_MM);
    v = (v > 0.f) ? v : 0.f;
    if (xh) xh[idx] = __float2half_rn(v);
    if (xf) xf[idx] = v;
}

// -------------------- host launch --------------------
extern "C" void kernel_launch(void* const* d_in, const int* in_sizes, int n_in,
                              void* d_out, int out_size) {
    const float* nf  = (const float*)d_in[0];
    const float* inc = (const float*)d_in[1];
    const float* ef  = (const float*)d_in[2];
    const float* Wn  = (const float*)d_in[3];
    const float* bn  = (const float*)d_in[4];
    const float* We  = (const float*)d_in[5];
    const float* be  = (const float*)d_in[6];
    const float* Wa  = (const float*)d_in[7];
    const float* ba  = (const float*)d_in[8];
    const float* Wo  = (const float*)d_in[9];
    const float* bo  = (const float*)d_in[10];
    float* out = (float*)d_out;

    __half *p_inc_h, *p_te_h, *p_Wc_h, *p_nf_h, *p_ef_h, *p_Wn_h, *p_Wo_h, *p_upd_h, *p_x_h;
    float *p_agg, *p_deg, *p_bc, *p_ob;
    unsigned *p_mn, *p_mx;
    cudaGetSymbolAddress((void**)&p_inc_h, g_inc_h);
    cudaGetSymbolAddress((void**)&p_te_h,  g_te_h);
    cudaGetSymbolAddress((void**)&p_Wc_h,  g_Wc_h);
    cudaGetSymbolAddress((void**)&p_nf_h,  g_nf_h);
    cudaGetSymbolAddress((void**)&p_ef_h,  g_ef_h);
    cudaGetSymbolAddress((void**)&p_Wn_h,  g_Wn_h);
    cudaGetSymbolAddress((void**)&p_Wo_h,  g_Wo_h);
    cudaGetSymbolAddress((void**)&p_upd_h, g_upd_h);
    cudaGetSymbolAddress((void**)&p_x_h,   g_x_h);
    cudaGetSymbolAddress((void**)&p_agg,   g_agg);
    cudaGetSymbolAddress((void**)&p_deg,   g_deg);
    cudaGetSymbolAddress((void**)&p_bc,    g_bc);
    cudaGetSymbolAddress((void**)&p_ob,    g_ob);
    cudaGetSymbolAddress((void**)&p_mn,    g_mn);
    cudaGetSymbolAddress((void**)&p_mx,    g_mx);

    static bool attr_set = false;
    if (!attr_set) {
        cudaFuncSetAttribute(hgemm_kernel<false, false>,
                             cudaFuncAttributeMaxDynamicSharedMemorySize, HGEMM_SMEM);
        cudaFuncSetAttribute(hgemm_kernel<true, false>,
                             cudaFuncAttributeMaxDynamicSharedMemorySize, HGEMM_SMEM);
        cudaFuncSetAttribute(hgemm_kernel<false, true>,
                             cudaFuncAttributeMaxDynamicSharedMemorySize, HGEMM_SMEM);
        cudaFuncSetAttribute(tn_score_kernel,
                             cudaFuncAttributeMaxDynamicSharedMemorySize, FT_SMEM);
        attr_set = true;
    }

    // ---- converts / packs / degree / minmax init ----
    conv_all_kernel<<<1792, 256>>>(nf, ef, Wn, Wo, p_nf_h, p_ef_h, p_Wn_h, p_Wo_h);
    pack_kernel<<<512, 256>>>(We, be, p_Wc_h, p_bc, p_mn, p_mx);
    deg_fuse_kernel<<<N_NODES, 256>>>(inc, p_deg, p_inc_h);

    // ---- te_all = ef @ Wc + bc (fp16 out) ----
    hgemm_kernel<true, false><<<dim3(8, N_EDGES / 128), 256, HGEMM_SMEM>>>(
        p_ef_h, p_Wc_h, p_te_h, N_EDGES, 1024, 128, p_bc, nullptr, nullptr, nullptr);
    // ---- agg = (inc @ te)/deg ----
    hgemm_kernel<false, false><<<dim3(8, N_NODES / 128), 256, HGEMM_SMEM>>>(
        p_inc_h, p_te_h, p_agg, N_NODES, 1024, N_EDGES, nullptr, p_deg, nullptr, nullptr);

    // ---- sequential heads ----
    for (int h = 0; h < NHEADS; h++) {
        const __half* xin = (h == 0) ? p_nf_h : p_x_h;
        // fused tn + score + sigmoid + update
        tn_score_kernel<<<N_NODES / 64, 256, FT_SMEM>>>(
            xin, p_Wn_h + (size_t)h * 128 * 256, bn + (size_t)h * 256,
            Wa + (size_t)h * 256, ba + h, p_agg + (size_t)h * 256, p_upd_h);
        // out = upd @ Wo + bo, fused column min/max
        hgemm_kernel<false, true><<<dim3(1, N_NODES / 128), 256, HGEMM_SMEM>>>(
            p_upd_h, p_Wo_h + (size_t)h * 256 * 128, p_ob, N_NODES, OUTD, HID,
            bo + (size_t)h * 128, nullptr, p_mn + h * OUTD, p_mx + h * OUTD);
        // normalize + relu
        norm_relu_kernel<<<(N_NODES * OUTD) / 256, 256>>>(
            p_ob, p_mn + h * OUTD, p_mx + h * OUTD,
            (h == NHEADS - 1) ? nullptr : p_x_h,
            (h == NHEADS - 1) ? out : nullptr);
    }
}

// round 15
// speedup vs baseline: 1.0040x; 1.0040x over previous
#include <cuda_runtime.h>
#include <cuda_fp16.h>
#include <math.h>
#include <stdint.h>

#define N_NODES 8192
#define N_EDGES 4096
#define HID     256
#define OUTD    128
#define NHEADS  4
#define EPS_AGG 1e-8f
#define EPS_MM  1e-8f

// -------------------- scratch (no allocations allowed) --------------------
__device__ __half   g_inc_h[(size_t)N_NODES * N_EDGES];   // fp16 incidence (64MB)
__device__ __half   g_te_h[(size_t)N_EDGES * 1024];       // fp16 te_all [4096,1024]
__device__ float    g_agg[(size_t)N_NODES * 1024];
__device__ float    g_deg[N_NODES];
__device__ __half   g_Wc_h[128 * 1024];
__device__ float    g_bc[1024];
__device__ __half   g_nf_h[(size_t)N_NODES * 128];
__device__ __half   g_ef_h[(size_t)N_EDGES * 128];
__device__ __half   g_Wn_h[4 * 128 * 256];
__device__ __half   g_Wo_h[4 * 256 * 128];
__device__ __half   g_upd_h[(size_t)N_NODES * HID];
__device__ float    g_ob[(size_t)N_NODES * OUTD];
__device__ __half   g_x_h[(size_t)N_NODES * OUTD];
__device__ unsigned g_mn[NHEADS * OUTD];
__device__ unsigned g_mx[NHEADS * OUTD];

// -------------------- helpers --------------------
__device__ __forceinline__ unsigned enc_f(float f) {
    unsigned u = __float_as_uint(f);
    return (u & 0x80000000u) ? ~u : (u | 0x80000000u);
}
__device__ __forceinline__ float dec_f(unsigned u) {
    return (u & 0x80000000u) ? __uint_as_float(u ^ 0x80000000u)
                             : __uint_as_float(~u);
}
__device__ __forceinline__ void cp16(void* dst, const void* src) {
    unsigned d = (unsigned)__cvta_generic_to_shared(dst);
    asm volatile("cp.async.cg.shared.global [%0], [%1], 16;\n" :: "r"(d), "l"(src));
}
__device__ __forceinline__ void ldsm_x4(unsigned& d0, unsigned& d1, unsigned& d2, unsigned& d3,
                                        const void* p) {
    unsigned a = (unsigned)__cvta_generic_to_shared(p);
    asm volatile("ldmatrix.sync.aligned.m8n8.x4.shared.b16 {%0,%1,%2,%3}, [%4];\n"
                 : "=r"(d0), "=r"(d1), "=r"(d2), "=r"(d3) : "r"(a));
}
__device__ __forceinline__ void ldsm_x4_t(unsigned& d0, unsigned& d1, unsigned& d2, unsigned& d3,
                                          const void* p) {
    unsigned a = (unsigned)__cvta_generic_to_shared(p);
    asm volatile("ldmatrix.sync.aligned.m8n8.x4.trans.shared.b16 {%0,%1,%2,%3}, [%4];\n"
                 : "=r"(d0), "=r"(d1), "=r"(d2), "=r"(d3) : "r"(a));
}
__device__ __forceinline__ void mma_f16(float c[4], const unsigned a[4],
                                        unsigned b0, unsigned b1) {
    asm volatile(
        "mma.sync.aligned.m16n8k16.row.col.f32.f16.f16.f32 "
        "{%0,%1,%2,%3}, {%4,%5,%6,%7}, {%8,%9}, {%0,%1,%2,%3};\n"
        : "+f"(c[0]), "+f"(c[1]), "+f"(c[2]), "+f"(c[3])
        : "r"(a[0]), "r"(a[1]), "r"(a[2]), "r"(a[3]), "r"(b0), "r"(b1));
}

// -------------------- fused f32->f16 converts (one launch) --------------------
__global__ void conv_all_kernel(const float* __restrict__ nf, const float* __restrict__ ef,
                                const float* __restrict__ Wn, const float* __restrict__ Wo,
                                __half* __restrict__ nfh, __half* __restrict__ efh,
                                __half* __restrict__ Wnh, __half* __restrict__ Woh) {
    int i = blockIdx.x * 256 + threadIdx.x;
    const float* src; __half* dst; int off;
    if (i < 262144)        { src = nf; dst = nfh; off = i; }
    else if (i < 393216)   { src = ef; dst = efh; off = i - 262144; }
    else if (i < 425984)   { src = Wn; dst = Wnh; off = i - 393216; }
    else                   { src = Wo; dst = Woh; off = i - 425984; }
    float4 v = reinterpret_cast<const float4*>(src)[off];
    __half2* o = reinterpret_cast<__half2*>(dst) + 2 * off;
    o[0] = __floats2half2_rn(v.x, v.y);
    o[1] = __floats2half2_rn(v.z, v.w);
}

// -------------------- pack We/be + init minmax --------------------
__global__ void pack_kernel(const float* __restrict__ We, const float* __restrict__ be,
                            __half* __restrict__ Wc, float* __restrict__ bc,
                            unsigned* __restrict__ mn, unsigned* __restrict__ mx) {
    int idx = blockIdx.x * blockDim.x + threadIdx.x;
    if (idx < 128 * 1024) {
        int k = idx / 1024;
        int n = idx % 1024;
        int h = n / 256, j = n % 256;
        Wc[idx] = __float2half_rn(We[((size_t)h * 128 + k) * 256 + j]);
    }
    if (idx < 1024) {
        int h = idx / 256, j = idx % 256;
        bc[idx] = be[h * 256 + j];
    }
    if (idx < NHEADS * OUTD) {
        mn[idx] = 0xFFFFFFFFu;
        mx[idx] = 0u;
    }
}

// -------------------- row degree + fp16 copy of incidence --------------------
__global__ void deg_fuse_kernel(const float* __restrict__ inc, float* __restrict__ deg,
                                __half* __restrict__ inc_h) {
    int row = blockIdx.x;
    const float4* p = reinterpret_cast<const float4*>(inc + (size_t)row * N_EDGES);
    __half2* q = reinterpret_cast<__half2*>(inc_h + (size_t)row * N_EDGES);
    float s = 0.f;
    for (int i = threadIdx.x; i < N_EDGES / 4; i += blockDim.x) {
        float4 v = p[i];
        s += (v.x + v.y) + (v.z + v.w);
        q[2 * i]     = __floats2half2_rn(v.x, v.y);
        q[2 * i + 1] = __floats2half2_rn(v.z, v.w);
    }
    #pragma unroll
    for (int o = 16; o; o >>= 1) s += __shfl_xor_sync(0xFFFFFFFFu, s, o);
    __shared__ float ws[8];
    int w = threadIdx.x >> 5, l = threadIdx.x & 31;
    if (l == 0) ws[w] = s;
    __syncthreads();
    if (threadIdx.x == 0) {
        float t = 0.f;
        #pragma unroll
        for (int i = 0; i < 8; i++) t += ws[i];
        deg[row] = t + EPS_AGG;
    }
}

// ==================== mma.sync fp16 GEMM (te + agg + out) ====================
#define BKh      32
#define A_STRIDE 40
#define B_STRIDE 136
#define A_STAGE  (128 * A_STRIDE)
#define B_STAGE  (32 * B_STRIDE)
#define NSTAGE   3
#define HGEMM_SMEM ((NSTAGE * (A_STAGE + B_STAGE)) * 2)

template <bool OUT_HALF, bool MINMAX>
__global__ __launch_bounds__(256, 2)
void hgemm_kernel(const __half* __restrict__ A, const __half* __restrict__ B,
                  void* __restrict__ Cv, int M, int N, int K,
                  const float* __restrict__ bias, const float* __restrict__ degv,
                  unsigned* __restrict__ gmn, unsigned* __restrict__ gmx) {
    extern __shared__ __half sh[];
    __half* As = sh;
    __half* Bs = sh + NSTAGE * A_STAGE;
    __shared__ unsigned cmn[128], cmx[128];

    const int tid  = threadIdx.x;
    const int lane = tid & 31;
    const int warp = tid >> 5;
    const int wm = (warp >> 2) * 64;
    const int wn = (warp & 3) * 32;
    const int g  = lane >> 2;
    const int tg = lane & 3;
    const int l16  = lane & 15;
    const int lhi8 = (lane >> 4) * 8;

    const int by = blockIdx.y * 128;
    const int bx = blockIdx.x * 128;

    if (MINMAX && tid < 128) { cmn[tid] = 0xFFFFFFFFu; cmx[tid] = 0u; }

    float acc[4][4][4];
    #pragma unroll
    for (int i = 0; i < 4; i++)
        #pragma unroll
        for (int j = 0; j < 4; j++)
            #pragma unroll
            for (int r = 0; r < 4; r++) acc[i][j][r] = 0.f;

    #define LOAD_STAGE(s, k0)                                                    \
        do {                                                                     \
            _Pragma("unroll")                                                    \
            for (int i = 0; i < 2; i++) {                                        \
                int c = tid + i * 256;                                           \
                int row = c >> 2, col = (c & 3) * 8;                             \
                cp16(As + (s) * A_STAGE + row * A_STRIDE + col,                  \
                     A + (size_t)(by + row) * K + (k0) + col);                   \
            }                                                                    \
            _Pragma("unroll")                                                    \
            for (int i = 0; i < 2; i++) {                                        \
                int c = tid + i * 256;                                           \
                int row = c >> 4, col = (c & 15) * 8;                            \
                cp16(Bs + (s) * B_STAGE + row * B_STRIDE + col,                  \
                     B + (size_t)((k0) + row) * N + bx + col);                   \
            }                                                                    \
        } while (0)

    const int nIt = K / BKh;

    LOAD_STAGE(0, 0);
    asm volatile("cp.async.commit_group;\n" ::: "memory");
    LOAD_STAGE(1, BKh);
    asm volatile("cp.async.commit_group;\n" ::: "memory");

    for (int it = 0; it < nIt; it++) {
        asm volatile("cp.async.wait_group 1;\n" ::: "memory");
        __syncthreads();
        if (it + 2 < nIt) {
            int s2 = (it + 2) % NSTAGE;
            LOAD_STAGE(s2, (it + 2) * BKh);
        }
        asm volatile("cp.async.commit_group;\n" ::: "memory");

        const int s = it % NSTAGE;
        const __half* Ab = As + s * A_STAGE;
        const __half* Bb = Bs + s * B_STAGE;

        #pragma unroll
        for (int kb = 0; kb < BKh; kb += 16) {
            unsigned af[4][4];
            #pragma unroll
            for (int mt = 0; mt < 4; mt++) {
                const __half* p = Ab + (wm + mt * 16 + l16) * A_STRIDE + kb + lhi8;
                ldsm_x4(af[mt][0], af[mt][1], af[mt][2], af[mt][3], p);
            }
            unsigned bf[2][4];
            #pragma unroll
            for (int pr = 0; pr < 2; pr++) {
                const __half* p = Bb + (kb + l16) * B_STRIDE + wn + pr * 16 + lhi8;
                ldsm_x4_t(bf[pr][0], bf[pr][1], bf[pr][2], bf[pr][3], p);
            }
            #pragma unroll
            for (int mt = 0; mt < 4; mt++)
                #pragma unroll
                for (int nt = 0; nt < 4; nt++)
                    mma_f16(acc[mt][nt], af[mt],
                            bf[nt >> 1][(nt & 1) * 2], bf[nt >> 1][(nt & 1) * 2 + 1]);
        }
        __syncthreads();
    }

    #pragma unroll
    for (int mt = 0; mt < 4; mt++) {
        int r0 = by + wm + mt * 16 + g;
        float d0 = degv ? (1.0f / degv[r0])     : 1.0f;
        float d1 = degv ? (1.0f / degv[r0 + 8]) : 1.0f;
        #pragma unroll
        for (int nt = 0; nt < 4; nt++) {
            int col = bx + wn + nt * 8 + tg * 2;
            float b0 = 0.f, b1 = 0.f;
            if (bias) { b0 = bias[col]; b1 = bias[col + 1]; }
            float v00 = (acc[mt][nt][0] + b0) * d0;
            float v01 = (acc[mt][nt][1] + b1) * d0;
            float v10 = (acc[mt][nt][2] + b0) * d1;
            float v11 = (acc[mt][nt][3] + b1) * d1;
            if (OUT_HALF) {
                __half* C = (__half*)Cv;
                *reinterpret_cast<__half2*>(C + (size_t)r0 * N + col) =
                    __floats2half2_rn(v00, v01);
                *reinterpret_cast<__half2*>(C + (size_t)(r0 + 8) * N + col) =
                    __floats2half2_rn(v10, v11);
            } else {
                float* C = (float*)Cv;
                *reinterpret_cast<float2*>(C + (size_t)r0 * N + col)       = make_float2(v00, v01);
                *reinterpret_cast<float2*>(C + (size_t)(r0 + 8) * N + col) = make_float2(v10, v11);
            }
            // store back (biased) for minmax pass below
            acc[mt][nt][0] = v00; acc[mt][nt][1] = v01;
            acc[mt][nt][2] = v10; acc[mt][nt][3] = v11;
        }
    }

    if (MINMAX) {
        __syncthreads();
        // per-thread pre-reduce over mt (same columns), then smem atomics
        #pragma unroll
        for (int nt = 0; nt < 4; nt++) {
            #pragma unroll
            for (int p = 0; p < 2; p++) {
                int col = wn + nt * 8 + tg * 2 + p;   // bx==0 for N=128
                unsigned lmn = 0xFFFFFFFFu, lmx = 0u;
                #pragma unroll
                for (int mt = 0; mt < 4; mt++) {
                    unsigned e0 = enc_f(acc[mt][nt][p]);
                    unsigned e1 = enc_f(acc[mt][nt][p + 2]);
                    lmn = min(lmn, min(e0, e1));
                    lmx = max(lmx, max(e0, e1));
                }
                atomicMin(&cmn[col], lmn);
                atomicMax(&cmx[col], lmx);
            }
        }
        __syncthreads();
        if (tid < 128) {
            atomicMin(&gmn[tid], cmn[tid]);
            atomicMax(&gmx[tid], cmx[tid]);
        }
    }
    #undef LOAD_STAGE
}

// ==================== fused tn GEMM + score + sigmoid + update ====================
// CTA tile 64x256 (full HID), K=128, 8 warps (2M x 4N), warp tile 32x64.
// upd[r,:] = sigmoid(leaky(sum_c (tn+agg)(r,c)*Wa[c] + ba)) * agg[r,:] + tn[r,:]
#define FT_APITCH 136
#define FT_BPITCH 264
#define FT_SMEM   ((64 * FT_APITCH + 128 * FT_BPITCH) * 2)

__global__ __launch_bounds__(256, 1)
void tn_score_kernel(const __half* __restrict__ X, const __half* __restrict__ Wn,
                     const float* __restrict__ bn, const float* __restrict__ Wa,
                     const float* __restrict__ ba, const float* __restrict__ aggh,
                     __half* __restrict__ upd) {
    extern __shared__ __half sh[];
    __half* As = sh;                       // [64][136]
    __half* Bs = sh + 64 * FT_APITCH;      // [128][264]
    __shared__ float s_wa[256], s_bn[256];
    __shared__ float s_row[64][4];
    __shared__ float s_co[64];

    const int tid  = threadIdx.x;
    const int lane = tid & 31;
    const int warp = tid >> 5;
    const int wm = (warp >> 2) * 32;
    const int wn = (warp & 3) * 64;
    const int g  = lane >> 2;
    const int tg = lane & 3;
    const int l16  = lane & 15;
    const int lhi8 = (lane >> 4) * 8;
    const int by = blockIdx.x * 64;

    // A: 64 rows x 128 halves (4 cp16/thread)
    #pragma unroll
    for (int i = 0; i < 4; i++) {
        int c = tid + i * 256;
        int row = c >> 4, cw = c & 15;
        cp16(As + row * FT_APITCH + cw * 8, X + (size_t)(by + row) * 128 + cw * 8);
    }
    // B: 128 rows x 256 halves (16 cp16/thread)
    #pragma unroll
    for (int i = 0; i < 16; i++) {
        int c = tid + i * 256;
        int row = c >> 5, cw = c & 31;
        cp16(Bs + row * FT_BPITCH + cw * 8, Wn + (size_t)row * 256 + cw * 8);
    }
    asm volatile("cp.async.commit_group;\n" ::: "memory");
    if (tid < 256) { s_wa[tid] = Wa[tid]; s_bn[tid] = bn[tid]; }
    asm volatile("cp.async.wait_group 0;\n" ::: "memory");
    __syncthreads();

    float acc[2][8][4];
    #pragma unroll
    for (int i = 0; i < 2; i++)
        #pragma unroll
        for (int j = 0; j < 8; j++)
            #pragma unroll
            for (int r = 0; r < 4; r++) acc[i][j][r] = 0.f;

    #pragma unroll
    for (int kb = 0; kb < 128; kb += 16) {
        unsigned af[2][4];
        #pragma unroll
        for (int mt = 0; mt < 2; mt++) {
            const __half* p = As + (wm + mt * 16 + l16) * FT_APITCH + kb + lhi8;
            ldsm_x4(af[mt][0], af[mt][1], af[mt][2], af[mt][3], p);
        }
        unsigned bf[4][4];
        #pragma unroll
        for (int pr = 0; pr < 4; pr++) {
            const __half* p = Bs + (kb + l16) * FT_BPITCH + wn + pr * 16 + lhi8;
            ldsm_x4_t(bf[pr][0], bf[pr][1], bf[pr][2], bf[pr][3], p);
        }
        #pragma unroll
        for (int mt = 0; mt < 2; mt++)
            #pragma unroll
            for (int nt = 0; nt < 8; nt++)
                mma_f16(acc[mt][nt], af[mt],
                        bf[nt >> 1][(nt & 1) * 2], bf[nt >> 1][(nt & 1) * 2 + 1]);
    }

    // ---- epilogue: bias, load agg, score partials ----
    float av[2][8][4];
    float sp[2][2] = {{0.f, 0.f}, {0.f, 0.f}};
    #pragma unroll
    for (int mt = 0; mt < 2; mt++) {
        int gr0 = by + wm + mt * 16 + g;
        #pragma unroll
        for (int nt = 0; nt < 8; nt++) {
            int col = wn + nt * 8 + tg * 2;
            float2 a0 = *reinterpret_cast<const float2*>(aggh + (size_t)gr0 * 1024 + col);
            float2 a1 = *reinterpret_cast<const float2*>(aggh + (size_t)(gr0 + 8) * 1024 + col);
            av[mt][nt][0] = a0.x; av[mt][nt][1] = a0.y;
            av[mt][nt][2] = a1.x; av[mt][nt][3] = a1.y;
            float t0 = acc[mt][nt][0] + s_bn[col];
            float t1 = acc[mt][nt][1] + s_bn[col + 1];
            float t2 = acc[mt][nt][2] + s_bn[col];
            float t3 = acc[mt][nt][3] + s_bn[col + 1];
            acc[mt][nt][0] = t0; acc[mt][nt][1] = t1;
            acc[mt][nt][2] = t2; acc[mt][nt][3] = t3;
            sp[mt][0] += (t0 + a0.x) * s_wa[col] + (t1 + a0.y) * s_wa[col + 1];
            sp[mt][1] += (t2 + a1.x) * s_wa[col] + (t3 + a1.y) * s_wa[col + 1];
        }
    }
    // reduce over tg (lanes g*4..g*4+3)
    #pragma unroll
    for (int mt = 0; mt < 2; mt++)
        #pragma unroll
        for (int hf = 0; hf < 2; hf++) {
            sp[mt][hf] += __shfl_xor_sync(0xFFFFFFFFu, sp[mt][hf], 1);
            sp[mt][hf] += __shfl_xor_sync(0xFFFFFFFFu, sp[mt][hf], 2);
        }
    if (tg == 0) {
        #pragma unroll
        for (int mt = 0; mt < 2; mt++) {
            s_row[wm + mt * 16 + g][warp & 3]     = sp[mt][0];
            s_row[wm + mt * 16 + g + 8][warp & 3] = sp[mt][1];
        }
    }
    __syncthreads();
    if (tid < 64) {
        float s = s_row[tid][0] + s_row[tid][1] + s_row[tid][2] + s_row[tid][3] + ba[0];
        s = (s > 0.f) ? s : 0.2f * s;
        s_co[tid] = 1.0f / (1.0f + expf(-s));
    }
    __syncthreads();

    #pragma unroll
    for (int mt = 0; mt < 2; mt++) {
        int lr = wm + mt * 16 + g;
        float c0 = s_co[lr];
        float c1 = s_co[lr + 8];
        int gr0 = by + lr;
        #pragma unroll
        for (int nt = 0; nt < 8; nt++) {
            int col = wn + nt * 8 + tg * 2;
            *reinterpret_cast<__half2*>(upd + (size_t)gr0 * 256 + col) =
                __floats2half2_rn(c0 * av[mt][nt][0] + acc[mt][nt][0],
                                  c0 * av[mt][nt][1] + acc[mt][nt][1]);
            *reinterpret_cast<__half2*>(upd + (size_t)(gr0 + 8) * 256 + col) =
                __floats2half2_rn(c1 * av[mt][nt][2] + acc[mt][nt][2],
                                  c1 * av[mt][nt][3] + acc[mt][nt][3]);
        }
    }
}

// -------------------- normalize + relu (dual output) --------------------
__global__ void norm_relu_kernel(const float* __restrict__ ob,
                                 const unsigned* __restrict__ mnU,
                                 const unsigned* __restrict__ mxU,
                                 __half* __restrict__ xh, float* __restrict__ xf) {
    int idx = blockIdx.x * blockDim.x + threadIdx.x;
    int c = idx & 127;
    float mn = dec_f(mnU[c]);
    float mx = dec_f(mxU[c]);
    float v = (ob[idx] - mn) / (mx - mn + EPS_MM);
    v = (v > 0.f) ? v : 0.f;
    if (xh) xh[idx] = __float2half_rn(v);
    if (xf) xf[idx] = v;
}

// -------------------- host launch --------------------
extern "C" void kernel_launch(void* const* d_in, const int* in_sizes, int n_in,
                              void* d_out, int out_size) {
    const float* nf  = (const float*)d_in[0];
    const float* inc = (const float*)d_in[1];
    const float* ef  = (const float*)d_in[2];
    const float* Wn  = (const float*)d_in[3];
    const float* bn  = (const float*)d_in[4];
    const float* We  = (const float*)d_in[5];
    const float* be  = (const float*)d_in[6];
    const float* Wa  = (const float*)d_in[7];
    const float* ba  = (const float*)d_in[8];
    const float* Wo  = (const float*)d_in[9];
    const float* bo  = (const float*)d_in[10];
    float* out = (float*)d_out;

    __half *p_inc_h, *p_te_h, *p_Wc_h, *p_nf_h, *p_ef_h, *p_Wn_h, *p_Wo_h, *p_upd_h, *p_x_h;
    float *p_agg, *p_deg, *p_bc, *p_ob;
    unsigned *p_mn, *p_mx;
    cudaGetSymbolAddress((void**)&p_inc_h, g_inc_h);
    cudaGetSymbolAddress((void**)&p_te_h,  g_te_h);
    cudaGetSymbolAddress((void**)&p_Wc_h,  g_Wc_h);
    cudaGetSymbolAddress((void**)&p_nf_h,  g_nf_h);
    cudaGetSymbolAddress((void**)&p_ef_h,  g_ef_h);
    cudaGetSymbolAddress((void**)&p_Wn_h,  g_Wn_h);
    cudaGetSymbolAddress((void**)&p_Wo_h,  g_Wo_h);
    cudaGetSymbolAddress((void**)&p_upd_h, g_upd_h);
    cudaGetSymbolAddress((void**)&p_x_h,   g_x_h);
    cudaGetSymbolAddress((void**)&p_agg,   g_agg);
    cudaGetSymbolAddress((void**)&p_deg,   g_deg);
    cudaGetSymbolAddress((void**)&p_bc,    g_bc);
    cudaGetSymbolAddress((void**)&p_ob,    g_ob);
    cudaGetSymbolAddress((void**)&p_mn,    g_mn);
    cudaGetSymbolAddress((void**)&p_mx,    g_mx);

    static bool attr_set = false;
    if (!attr_set) {
        cudaFuncSetAttribute(hgemm_kernel<false, false>,
                             cudaFuncAttributeMaxDynamicSharedMemorySize, HGEMM_SMEM);
        cudaFuncSetAttribute(hgemm_kernel<true, false>,
                             cudaFuncAttributeMaxDynamicSharedMemorySize, HGEMM_SMEM);
        cudaFuncSetAttribute(hgemm_kernel<false, true>,
                             cudaFuncAttributeMaxDynamicSharedMemorySize, HGEMM_SMEM);
        cudaFuncSetAttribute(tn_score_kernel,
                             cudaFuncAttributeMaxDynamicSharedMemorySize, FT_SMEM);
        attr_set = true;
    }

    // ---- converts / packs / degree / minmax init ----
    conv_all_kernel<<<1792, 256>>>(nf, ef, Wn, Wo, p_nf_h, p_ef_h, p_Wn_h, p_Wo_h);
    pack_kernel<<<512, 256>>>(We, be, p_Wc_h, p_bc, p_mn, p_mx);
    deg_fuse_kernel<<<N_NODES, 256>>>(inc, p_deg, p_inc_h);

    // ---- te_all = ef @ Wc + bc (fp16 out) ----
    hgemm_kernel<true, false><<<dim3(8, N_EDGES / 128), 256, HGEMM_SMEM>>>(
        p_ef_h, p_Wc_h, p_te_h, N_EDGES, 1024, 128, p_bc, nullptr, nullptr, nullptr);
    // ---- agg = (inc @ te)/deg ----
    hgemm_kernel<false, false><<<dim3(8, N_NODES / 128), 256, HGEMM_SMEM>>>(
        p_inc_h, p_te_h, p_agg, N_NODES, 1024, N_EDGES, nullptr, p_deg, nullptr, nullptr);

    // ---- sequential heads ----
    for (int h = 0; h < NHEADS; h++) {
        const __half* xin = (h == 0) ? p_nf_h : p_x_h;
        // fused tn + score + sigmoid + update
        tn_score_kernel<<<N_NODES / 64, 256, FT_SMEM>>>(
            xin, p_Wn_h + (size_t)h * 128 * 256, bn + (size_t)h * 256,
            Wa + (size_t)h * 256, ba + h, p_agg + (size_t)h * 256, p_upd_h);
        // out = upd @ Wo + bo, fused column min/max
        hgemm_kernel<false, true><<<dim3(1, N_NODES / 128), 256, HGEMM_SMEM>>>(
            p_upd_h, p_Wo_h + (size_t)h * 256 * 128, p_ob, N_NODES, OUTD, HID,
            bo + (size_t)h * 128, nullptr, p_mn + h * OUTD, p_mx + h * OUTD);
        // normalize + relu
        norm_relu_kernel<<<(N_NODES * OUTD) / 256, 256>>>(
            p_ob, p_mn + h * OUTD, p_mx + h * OUTD,
            (h == NHEADS - 1) ? nullptr : p_x_h,
            (h == NHEADS - 1) ? out : nullptr);
    }
}

// round 16
// speedup vs baseline: 1.0065x; 1.0025x over previous
#include <cuda_runtime.h>
#include <cuda_fp16.h>
#include <math.h>
#include <stdint.h>

#define N_NODES 8192
#define N_EDGES 4096
#define HID     256
#define OUTD    128
#define NHEADS  4
#define EPS_AGG 1e-8f
#define EPS_MM  1e-8f

// -------------------- scratch (no allocations allowed) --------------------
__device__ __half   g_inc_h[(size_t)N_NODES * N_EDGES];   // fp16 incidence (64MB)
__device__ __half   g_te_h[(size_t)N_EDGES * 1024];       // fp16 te_all [4096,1024]
__device__ float    g_agg[(size_t)N_NODES * 1024];
__device__ float    g_deg[N_NODES];
__device__ __half   g_Wc_h[128 * 1024];
__device__ float    g_bc[1024];
__device__ __half   g_nf_h[(size_t)N_NODES * 128];
__device__ __half   g_ef_h[(size_t)N_EDGES * 128];
__device__ __half   g_Wn_h[4 * 128 * 256];
__device__ __half   g_Wo_h[4 * 256 * 128];
__device__ __half   g_upd_h[(size_t)N_NODES * HID];
__device__ float    g_ob[(size_t)N_NODES * OUTD];
__device__ __half   g_x_h[(size_t)N_NODES * OUTD];
__device__ unsigned g_mn[NHEADS * OUTD];
__device__ unsigned g_mx[NHEADS * OUTD];

// -------------------- helpers --------------------
__device__ __forceinline__ unsigned enc_f(float f) {
    unsigned u = __float_as_uint(f);
    return (u & 0x80000000u) ? ~u : (u | 0x80000000u);
}
__device__ __forceinline__ float dec_f(unsigned u) {
    return (u & 0x80000000u) ? __uint_as_float(u ^ 0x80000000u)
                             : __uint_as_float(~u);
}
__device__ __forceinline__ void cp16(void* dst, const void* src) {
    unsigned d = (unsigned)__cvta_generic_to_shared(dst);
    asm volatile("cp.async.cg.shared.global [%0], [%1], 16;\n" :: "r"(d), "l"(src));
}
__device__ __forceinline__ void ldsm_x4(unsigned& d0, unsigned& d1, unsigned& d2, unsigned& d3,
                                        const void* p) {
    unsigned a = (unsigned)__cvta_generic_to_shared(p);
    asm volatile("ldmatrix.sync.aligned.m8n8.x4.shared.b16 {%0,%1,%2,%3}, [%4];\n"
                 : "=r"(d0), "=r"(d1), "=r"(d2), "=r"(d3) : "r"(a));
}
__device__ __forceinline__ void ldsm_x4_t(unsigned& d0, unsigned& d1, unsigned& d2, unsigned& d3,
                                          const void* p) {
    unsigned a = (unsigned)__cvta_generic_to_shared(p);
    asm volatile("ldmatrix.sync.aligned.m8n8.x4.trans.shared.b16 {%0,%1,%2,%3}, [%4];\n"
                 : "=r"(d0), "=r"(d1), "=r"(d2), "=r"(d3) : "r"(a));
}
__device__ __forceinline__ void mma_f16(float c[4], const unsigned a[4],
                                        unsigned b0, unsigned b1) {
    asm volatile(
        "mma.sync.aligned.m16n8k16.row.col.f32.f16.f16.f32 "
        "{%0,%1,%2,%3}, {%4,%5,%6,%7}, {%8,%9}, {%0,%1,%2,%3};\n"
        : "+f"(c[0]), "+f"(c[1]), "+f"(c[2]), "+f"(c[3])
        : "r"(a[0]), "r"(a[1]), "r"(a[2]), "r"(a[3]), "r"(b0), "r"(b1));
}

// -------------------- fused f32->f16 converts (one launch) --------------------
__global__ void conv_all_kernel(const float* __restrict__ nf, const float* __restrict__ ef,
                                const float* __restrict__ Wn, const float* __restrict__ Wo,
                                __half* __restrict__ nfh, __half* __restrict__ efh,
                                __half* __restrict__ Wnh, __half* __restrict__ Woh) {
    int i = blockIdx.x * 256 + threadIdx.x;
    const float* src; __half* dst; int off;
    if (i < 262144)        { src = nf; dst = nfh; off = i; }
    else if (i < 393216)   { src = ef; dst = efh; off = i - 262144; }
    else if (i < 425984)   { src = Wn; dst = Wnh; off = i - 393216; }
    else                   { src = Wo; dst = Woh; off = i - 425984; }
    float4 v = reinterpret_cast<const float4*>(src)[off];
    __half2* o = reinterpret_cast<__half2*>(dst) + 2 * off;
    o[0] = __floats2half2_rn(v.x, v.y);
    o[1] = __floats2half2_rn(v.z, v.w);
}

// -------------------- pack We/be + init minmax --------------------
__global__ void pack_kernel(const float* __restrict__ We, const float* __restrict__ be,
                            __half* __restrict__ Wc, float* __restrict__ bc,
                            unsigned* __restrict__ mn, unsigned* __restrict__ mx) {
    int idx = blockIdx.x * blockDim.x + threadIdx.x;
    if (idx < 128 * 1024) {
        int k = idx / 1024;
        int n = idx % 1024;
        int h = n / 256, j = n % 256;
        Wc[idx] = __float2half_rn(We[((size_t)h * 128 + k) * 256 + j]);
    }
    if (idx < 1024) {
        int h = idx / 256, j = idx % 256;
        bc[idx] = be[h * 256 + j];
    }
    if (idx < NHEADS * OUTD) {
        mn[idx] = 0xFFFFFFFFu;
        mx[idx] = 0u;
    }
}

// -------------------- row degree + fp16 copy of incidence --------------------
__global__ void deg_fuse_kernel(const float* __restrict__ inc, float* __restrict__ deg,
                                __half* __restrict__ inc_h) {
    int row = blockIdx.x;
    const float4* p = reinterpret_cast<const float4*>(inc + (size_t)row * N_EDGES);
    __half2* q = reinterpret_cast<__half2*>(inc_h + (size_t)row * N_EDGES);
    float s = 0.f;
    for (int i = threadIdx.x; i < N_EDGES / 4; i += blockDim.x) {
        float4 v = p[i];
        s += (v.x + v.y) + (v.z + v.w);
        q[2 * i]     = __floats2half2_rn(v.x, v.y);
        q[2 * i + 1] = __floats2half2_rn(v.z, v.w);
    }
    #pragma unroll
    for (int o = 16; o; o >>= 1) s += __shfl_xor_sync(0xFFFFFFFFu, s, o);
    __shared__ float ws[8];
    int w = threadIdx.x >> 5, l = threadIdx.x & 31;
    if (l == 0) ws[w] = s;
    __syncthreads();
    if (threadIdx.x == 0) {
        float t = 0.f;
        #pragma unroll
        for (int i = 0; i < 8; i++) t += ws[i];
        deg[row] = t + EPS_AGG;
    }
}

// ==================== mma.sync fp16 GEMM (te + agg + out) ====================
#define BKh      32
#define A_STRIDE 40
#define B_STRIDE 136
#define A_STAGE  (128 * A_STRIDE)
#define B_STAGE  (32 * B_STRIDE)
#define NSTAGE   3
#define HGEMM_SMEM ((NSTAGE * (A_STAGE + B_STAGE)) * 2)

template <bool OUT_HALF, bool MINMAX>
__global__ __launch_bounds__(256, 2)
void hgemm_kernel(const __half* __restrict__ A, const __half* __restrict__ B,
                  void* __restrict__ Cv, int M, int N, int K,
                  const float* __restrict__ bias, const float* __restrict__ degv,
                  unsigned* __restrict__ gmn, unsigned* __restrict__ gmx) {
    extern __shared__ __half sh[];
    __half* As = sh;
    __half* Bs = sh + NSTAGE * A_STAGE;
    __shared__ unsigned cmn[128], cmx[128];

    const int tid  = threadIdx.x;
    const int lane = tid & 31;
    const int warp = tid >> 5;
    const int wm = (warp >> 2) * 64;
    const int wn = (warp & 3) * 32;
    const int g  = lane >> 2;
    const int tg = lane & 3;
    const int l16  = lane & 15;
    const int lhi8 = (lane >> 4) * 8;

    const int by = blockIdx.y * 128;
    const int bx = blockIdx.x * 128;

    if (MINMAX && tid < 128) { cmn[tid] = 0xFFFFFFFFu; cmx[tid] = 0u; }

    float acc[4][4][4];
    #pragma unroll
    for (int i = 0; i < 4; i++)
        #pragma unroll
        for (int j = 0; j < 4; j++)
            #pragma unroll
            for (int r = 0; r < 4; r++) acc[i][j][r] = 0.f;

    #define LOAD_STAGE(s, k0)                                                    \
        do {                                                                     \
            _Pragma("unroll")                                                    \
            for (int i = 0; i < 2; i++) {                                        \
                int c = tid + i * 256;                                           \
                int row = c >> 2, col = (c & 3) * 8;                             \
                cp16(As + (s) * A_STAGE + row * A_STRIDE + col,                  \
                     A + (size_t)(by + row) * K + (k0) + col);                   \
            }                                                                    \
            _Pragma("unroll")                                                    \
            for (int i = 0; i < 2; i++) {                                        \
                int c = tid + i * 256;                                           \
                int row = c >> 4, col = (c & 15) * 8;                            \
                cp16(Bs + (s) * B_STAGE + row * B_STRIDE + col,                  \
                     B + (size_t)((k0) + row) * N + bx + col);                   \
            }                                                                    \
        } while (0)

    const int nIt = K / BKh;

    LOAD_STAGE(0, 0);
    asm volatile("cp.async.commit_group;\n" ::: "memory");
    LOAD_STAGE(1, BKh);
    asm volatile("cp.async.commit_group;\n" ::: "memory");

    for (int it = 0; it < nIt; it++) {
        asm volatile("cp.async.wait_group 1;\n" ::: "memory");
        __syncthreads();
        if (it + 2 < nIt) {
            int s2 = (it + 2) % NSTAGE;
            LOAD_STAGE(s2, (it + 2) * BKh);
        }
        asm volatile("cp.async.commit_group;\n" ::: "memory");

        const int s = it % NSTAGE;
        const __half* Ab = As + s * A_STAGE;
        const __half* Bb = Bs + s * B_STAGE;

        #pragma unroll
        for (int kb = 0; kb < BKh; kb += 16) {
            unsigned af[4][4];
            #pragma unroll
            for (int mt = 0; mt < 4; mt++) {
                const __half* p = Ab + (wm + mt * 16 + l16) * A_STRIDE + kb + lhi8;
                ldsm_x4(af[mt][0], af[mt][1], af[mt][2], af[mt][3], p);
            }
            unsigned bf[2][4];
            #pragma unroll
            for (int pr = 0; pr < 2; pr++) {
                const __half* p = Bb + (kb + l16) * B_STRIDE + wn + pr * 16 + lhi8;
                ldsm_x4_t(bf[pr][0], bf[pr][1], bf[pr][2], bf[pr][3], p);
            }
            #pragma unroll
            for (int mt = 0; mt < 4; mt++)
                #pragma unroll
                for (int nt = 0; nt < 4; nt++)
                    mma_f16(acc[mt][nt], af[mt],
                            bf[nt >> 1][(nt & 1) * 2], bf[nt >> 1][(nt & 1) * 2 + 1]);
        }
        __syncthreads();
    }

    #pragma unroll
    for (int mt = 0; mt < 4; mt++) {
        int r0 = by + wm + mt * 16 + g;
        float d0 = degv ? (1.0f / degv[r0])     : 1.0f;
        float d1 = degv ? (1.0f / degv[r0 + 8]) : 1.0f;
        #pragma unroll
        for (int nt = 0; nt < 4; nt++) {
            int col = bx + wn + nt * 8 + tg * 2;
            float b0 = 0.f, b1 = 0.f;
            if (bias) { b0 = bias[col]; b1 = bias[col + 1]; }
            float v00 = (acc[mt][nt][0] + b0) * d0;
            float v01 = (acc[mt][nt][1] + b1) * d0;
            float v10 = (acc[mt][nt][2] + b0) * d1;
            float v11 = (acc[mt][nt][3] + b1) * d1;
            if (OUT_HALF) {
                __half* C = (__half*)Cv;
                *reinterpret_cast<__half2*>(C + (size_t)r0 * N + col) =
                    __floats2half2_rn(v00, v01);
                *reinterpret_cast<__half2*>(C + (size_t)(r0 + 8) * N + col) =
                    __floats2half2_rn(v10, v11);
            } else {
                float* C = (float*)Cv;
                *reinterpret_cast<float2*>(C + (size_t)r0 * N + col)       = make_float2(v00, v01);
                *reinterpret_cast<float2*>(C + (size_t)(r0 + 8) * N + col) = make_float2(v10, v11);
            }
            // store back (biased) for minmax pass below
            acc[mt][nt][0] = v00; acc[mt][nt][1] = v01;
            acc[mt][nt][2] = v10; acc[mt][nt][3] = v11;
        }
    }

    if (MINMAX) {
        __syncthreads();
        // per-thread pre-reduce over mt (same columns), then smem atomics
        #pragma unroll
        for (int nt = 0; nt < 4; nt++) {
            #pragma unroll
            for (int p = 0; p < 2; p++) {
                int col = wn + nt * 8 + tg * 2 + p;   // bx==0 for N=128
                unsigned lmn = 0xFFFFFFFFu, lmx = 0u;
                #pragma unroll
                for (int mt = 0; mt < 4; mt++) {
                    unsigned e0 = enc_f(acc[mt][nt][p]);
                    unsigned e1 = enc_f(acc[mt][nt][p + 2]);
                    lmn = min(lmn, min(e0, e1));
                    lmx = max(lmx, max(e0, e1));
                }
                atomicMin(&cmn[col], lmn);
                atomicMax(&cmx[col], lmx);
            }
        }
        __syncthreads();
        if (tid < 128) {
            atomicMin(&gmn[tid], cmn[tid]);
            atomicMax(&gmx[tid], cmx[tid]);
        }
    }
    #undef LOAD_STAGE
}

// ==================== fused tn GEMM + score + sigmoid + update ====================
// CTA tile 64x256 (full HID), K=128, 8 warps (2M x 4N), warp tile 32x64.
// upd[r,:] = sigmoid(leaky(sum_c (tn+agg)(r,c)*Wa[c] + ba)) * agg[r,:] + tn[r,:]
#define FT_APITCH 136
#define FT_BPITCH 264
#define FT_SMEM   ((64 * FT_APITCH + 128 * FT_BPITCH) * 2)

__global__ __launch_bounds__(256, 1)
void tn_score_kernel(const __half* __restrict__ X, const __half* __restrict__ Wn,
                     const float* __restrict__ bn, const float* __restrict__ Wa,
                     const float* __restrict__ ba, const float* __restrict__ aggh,
                     __half* __restrict__ upd) {
    extern __shared__ __half sh[];
    __half* As = sh;                       // [64][136]
    __half* Bs = sh + 64 * FT_APITCH;      // [128][264]
    __shared__ float s_wa[256], s_bn[256];
    __shared__ float s_row[64][4];
    __shared__ float s_co[64];

    const int tid  = threadIdx.x;
    const int lane = tid & 31;
    const int warp = tid >> 5;
    const int wm = (warp >> 2) * 32;
    const int wn = (warp & 3) * 64;
    const int g  = lane >> 2;
    const int tg = lane & 3;
    const int l16  = lane & 15;
    const int lhi8 = (lane >> 4) * 8;
    const int by = blockIdx.x * 64;

    // A: 64 rows x 128 halves (4 cp16/thread)
    #pragma unroll
    for (int i = 0; i < 4; i++) {
        int c = tid + i * 256;
        int row = c >> 4, cw = c & 15;
        cp16(As + row * FT_APITCH + cw * 8, X + (size_t)(by + row) * 128 + cw * 8);
    }
    // B: 128 rows x 256 halves (16 cp16/thread)
    #pragma unroll
    for (int i = 0; i < 16; i++) {
        int c = tid + i * 256;
        int row = c >> 5, cw = c & 31;
        cp16(Bs + row * FT_BPITCH + cw * 8, Wn + (size_t)row * 256 + cw * 8);
    }
    asm volatile("cp.async.commit_group;\n" ::: "memory");
    if (tid < 256) { s_wa[tid] = Wa[tid]; s_bn[tid] = bn[tid]; }
    asm volatile("cp.async.wait_group 0;\n" ::: "memory");
    __syncthreads();

    float acc[2][8][4];
    #pragma unroll
    for (int i = 0; i < 2; i++)
        #pragma unroll
        for (int j = 0; j < 8; j++)
            #pragma unroll
            for (int r = 0; r < 4; r++) acc[i][j][r] = 0.f;

    #pragma unroll
    for (int kb = 0; kb < 128; kb += 16) {
        unsigned af[2][4];
        #pragma unroll
        for (int mt = 0; mt < 2; mt++) {
            const __half* p = As + (wm + mt * 16 + l16) * FT_APITCH + kb + lhi8;
            ldsm_x4(af[mt][0], af[mt][1], af[mt][2], af[mt][3], p);
        }
        unsigned bf[4][4];
        #pragma unroll
        for (int pr = 0; pr < 4; pr++) {
            const __half* p = Bs + (kb + l16) * FT_BPITCH + wn + pr * 16 + lhi8;
            ldsm_x4_t(bf[pr][0], bf[pr][1], bf[pr][2], bf[pr][3], p);
        }
        #pragma unroll
        for (int mt = 0; mt < 2; mt++)
            #pragma unroll
            for (int nt = 0; nt < 8; nt++)
                mma_f16(acc[mt][nt], af[mt],
                        bf[nt >> 1][(nt & 1) * 2], bf[nt >> 1][(nt & 1) * 2 + 1]);
    }

    // ---- epilogue: bias, load agg, score partials ----
    float av[2][8][4];
    float sp[2][2] = {{0.f, 0.f}, {0.f, 0.f}};
    #pragma unroll
    for (int mt = 0; mt < 2; mt++) {
        int gr0 = by + wm + mt * 16 + g;
        #pragma unroll
        for (int nt = 0; nt < 8; nt++) {
            int col = wn + nt * 8 + tg * 2;
            float2 a0 = *reinterpret_cast<const float2*>(aggh + (size_t)gr0 * 1024 + col);
            float2 a1 = *reinterpret_cast<const float2*>(aggh + (size_t)(gr0 + 8) * 1024 + col);
            av[mt][nt][0] = a0.x; av[mt][nt][1] = a0.y;
            av[mt][nt][2] = a1.x; av[mt][nt][3] = a1.y;
            float t0 = acc[mt][nt][0] + s_bn[col];
            float t1 = acc[mt][nt][1] + s_bn[col + 1];
            float t2 = acc[mt][nt][2] + s_bn[col];
            float t3 = acc[mt][nt][3] + s_bn[col + 1];
            acc[mt][nt][0] = t0; acc[mt][nt][1] = t1;
            acc[mt][nt][2] = t2; acc[mt][nt][3] = t3;
            sp[mt][0] += (t0 + a0.x) * s_wa[col] + (t1 + a0.y) * s_wa[col + 1];
            sp[mt][1] += (t2 + a1.x) * s_wa[col] + (t3 + a1.y) * s_wa[col + 1];
        }
    }
    // reduce over tg (lanes g*4..g*4+3)
    #pragma unroll
    for (int mt = 0; mt < 2; mt++)
        #pragma unroll
        for (int hf = 0; hf < 2; hf++) {
            sp[mt][hf] += __shfl_xor_sync(0xFFFFFFFFu, sp[mt][hf], 1);
            sp[mt][hf] += __shfl_xor_sync(0xFFFFFFFFu, sp[mt][hf], 2);
        }
    if (tg == 0) {
        #pragma unroll
        for (int mt = 0; mt < 2; mt++) {
            s_row[wm + mt * 16 + g][warp & 3]     = sp[mt][0];
            s_row[wm + mt * 16 + g + 8][warp & 3] = sp[mt][1];
        }
    }
    __syncthreads();
    if (tid < 64) {
        float s = s_row[tid][0] + s_row[tid][1] + s_row[tid][2] + s_row[tid][3] + ba[0];
        s = (s > 0.f) ? s : 0.2f * s;
        s_co[tid] = 1.0f / (1.0f + expf(-s));
    }
    __syncthreads();

    #pragma unroll
    for (int mt = 0; mt < 2; mt++) {
        int lr = wm + mt * 16 + g;
        float c0 = s_co[lr];
        float c1 = s_co[lr + 8];
        int gr0 = by + lr;
        #pragma unroll
        for (int nt = 0; nt < 8; nt++) {
            int col = wn + nt * 8 + tg * 2;
            *reinterpret_cast<__half2*>(upd + (size_t)gr0 * 256 + col) =
                __floats2half2_rn(c0 * av[mt][nt][0] + acc[mt][nt][0],
                                  c0 * av[mt][nt][1] + acc[mt][nt][1]);
            *reinterpret_cast<__half2*>(upd + (size_t)(gr0 + 8) * 256 + col) =
                __floats2half2_rn(c1 * av[mt][nt][2] + acc[mt][nt][2],
                                  c1 * av[mt][nt][3] + acc[mt][nt][3]);
        }
    }
}

// -------------------- normalize + relu (dual output) --------------------
__global__ void norm_relu_kernel(const float* __restrict__ ob,
                                 const unsigned* __restrict__ mnU,
                                 const unsigned* __restrict__ mxU,
                                 __half* __restrict__ xh, float* __restrict__ xf) {
    int idx = blockIdx.x * blockDim.x + threadIdx.x;
    int c = idx & 127;
    float mn = dec_f(mnU[c]);
    float mx = dec_f(mxU[c]);
    float v = (ob[idx] - mn) / (mx - mn + EPS_MM);
    v = (v > 0.f) ? v : 0.f;
    if (xh) xh[idx] = __float2half_rn(v);
    if (xf) xf[idx] = v;
}

// -------------------- host launch --------------------
extern "C" void kernel_launch(void* const* d_in, const int* in_sizes, int n_in,
                              void* d_out, int out_size) {
    const float* nf  = (const float*)d_in[0];
    const float* inc = (const float*)d_in[1];
    const float* ef  = (const float*)d_in[2];
    const float* Wn  = (const float*)d_in[3];
    const float* bn  = (const float*)d_in[4];
    const float* We  = (const float*)d_in[5];
    const float* be  = (const float*)d_in[6];
    const float* Wa  = (const float*)d_in[7];
    const float* ba  = (const float*)d_in[8];
    const float* Wo  = (const float*)d_in[9];
    const float* bo  = (const float*)d_in[10];
    float* out = (float*)d_out;

    __half *p_inc_h, *p_te_h, *p_Wc_h, *p_nf_h, *p_ef_h, *p_Wn_h, *p_Wo_h, *p_upd_h, *p_x_h;
    float *p_agg, *p_deg, *p_bc, *p_ob;
    unsigned *p_mn, *p_mx;
    cudaGetSymbolAddress((void**)&p_inc_h, g_inc_h);
    cudaGetSymbolAddress((void**)&p_te_h,  g_te_h);
    cudaGetSymbolAddress((void**)&p_Wc_h,  g_Wc_h);
    cudaGetSymbolAddress((void**)&p_nf_h,  g_nf_h);
    cudaGetSymbolAddress((void**)&p_ef_h,  g_ef_h);
    cudaGetSymbolAddress((void**)&p_Wn_h,  g_Wn_h);
    cudaGetSymbolAddress((void**)&p_Wo_h,  g_Wo_h);
    cudaGetSymbolAddress((void**)&p_upd_h, g_upd_h);
    cudaGetSymbolAddress((void**)&p_x_h,   g_x_h);
    cudaGetSymbolAddress((void**)&p_agg,   g_agg);
    cudaGetSymbolAddress((void**)&p_deg,   g_deg);
    cudaGetSymbolAddress((void**)&p_bc,    g_bc);
    cudaGetSymbolAddress((void**)&p_ob,    g_ob);
    cudaGetSymbolAddress((void**)&p_mn,    g_mn);
    cudaGetSymbolAddress((void**)&p_mx,    g_mx);

    static bool attr_set = false;
    if (!attr_set) {
        cudaFuncSetAttribute(hgemm_kernel<false, false>,
                             cudaFuncAttributeMaxDynamicSharedMemorySize, HGEMM_SMEM);
        cudaFuncSetAttribute(hgemm_kernel<true, false>,
                             cudaFuncAttributeMaxDynamicSharedMemorySize, HGEMM_SMEM);
        cudaFuncSetAttribute(hgemm_kernel<false, true>,
                             cudaFuncAttributeMaxDynamicSharedMemorySize, HGEMM_SMEM);
        cudaFuncSetAttribute(tn_score_kernel,
                             cudaFuncAttributeMaxDynamicSharedMemorySize, FT_SMEM);
        attr_set = true;
    }

    // ---- converts / packs / degree / minmax init ----
    conv_all_kernel<<<1792, 256>>>(nf, ef, Wn, Wo, p_nf_h, p_ef_h, p_Wn_h, p_Wo_h);
    pack_kernel<<<512, 256>>>(We, be, p_Wc_h, p_bc, p_mn, p_mx);
    deg_fuse_kernel<<<N_NODES, 256>>>(inc, p_deg, p_inc_h);

    // ---- te_all = ef @ Wc + bc (fp16 out) ----
    hgemm_kernel<true, false><<<dim3(8, N_EDGES / 128), 256, HGEMM_SMEM>>>(
        p_ef_h, p_Wc_h, p_te_h, N_EDGES, 1024, 128, p_bc, nullptr, nullptr, nullptr);
    // ---- agg = (inc @ te)/deg ----
    hgemm_kernel<false, false><<<dim3(8, N_NODES / 128), 256, HGEMM_SMEM>>>(
        p_inc_h, p_te_h, p_agg, N_NODES, 1024, N_EDGES, nullptr, p_deg, nullptr, nullptr);

    // ---- sequential heads ----
    for (int h = 0; h < NHEADS; h++) {
        const __half* xin = (h == 0) ? p_nf_h : p_x_h;
        // fused tn + score + sigmoid + update
        tn_score_kernel<<<N_NODES / 64, 256, FT_SMEM>>>(
            xin, p_Wn_h + (size_t)h * 128 * 256, bn + (size_t)h * 256,
            Wa + (size_t)h * 256, ba + h, p_agg + (size_t)h * 256, p_upd_h);
        // out = upd @ Wo + bo, fused column min/max
        hgemm_kernel<false, true><<<dim3(1, N_NODES / 128), 256, HGEMM_SMEM>>>(
            p_upd_h, p_Wo_h + (size_t)h * 256 * 128, p_ob, N_NODES, OUTD, HID,
            bo + (size_t)h * 128, nullptr, p_mn + h * OUTD, p_mx + h * OUTD);
        // normalize + relu
        norm_relu_kernel<<<(N_NODES * OUTD) / 256, 256>>>(
            p_ob, p_mn + h * OUTD, p_mx + h * OUTD,
            (h == NHEADS - 1) ? nullptr : p_x_h,
            (h == NHEADS - 1) ? out : nullptr);
    }
}